// round 6
// baseline (speedup 1.0000x reference)
#include <cuda_runtime.h>

#define N_NODES 50000
#define H 64
#define HC 32
#define HEADS 4
#define M_PATHS 2
#define E_EDGES 250000
#define P_LEN 3
#define FH 128
#define D 256
#define R_TOT (M_PATHS * N_NODES)      // 100000 rows
#define TILE 32
#define NTILES (R_TOT / TILE)          // 3125
#define ZST 260                         // smem row stride (floats), conflict-free
#define GRID_MLP 148
#define SMEM_MLP ((128 + TILE) * ZST * 4)   // 166400 B

// ---------------- scratch (device globals) ----------------------------------
__device__ float g_den[R_TOT * HEADS];          // per (path,node,head); -> recip
__device__ float g_a1[N_NODES * HEADS];         // celu3(features @ attn1_w.T)
__device__ float g_z[(size_t)R_TOT * D];        // raw  sum(ex*eft)  102.4 MB
__device__ float g_t1[(size_t)R_TOT * D];       // MLP layer-1 output 102.4 MB
__device__ float g_wsum[2];
__device__ float g_beta[2];

__device__ __forceinline__ float celu3f(float x) {
    return x > 0.0f ? x : 3.0f * expm1f(x * (1.0f / 3.0f));
}
__device__ __forceinline__ unsigned tf32r(float x) {
    unsigned r; asm("cvt.rna.tf32.f32 %0, %1;" : "=r"(r) : "f"(x)); return r;
}
__device__ __forceinline__ void mma_tf32(float* c, const unsigned* a,
                                         const unsigned* b) {
    asm volatile(
        "mma.sync.aligned.m16n8k8.row.col.f32.tf32.tf32.f32 "
        "{%0,%1,%2,%3}, {%4,%5,%6,%7}, {%8,%9}, {%0,%1,%2,%3};"
        : "+f"(c[0]), "+f"(c[1]), "+f"(c[2]), "+f"(c[3])
        : "r"(a[0]), "r"(a[1]), "r"(a[2]), "r"(a[3]), "r"(b[0]), "r"(b[1]));
}

// ---------------- zero everything -------------------------------------------
__global__ void zero_all_kernel() {
    int i = blockIdx.x * blockDim.x + threadIdx.x;
    int nz4 = R_TOT * D / 4;            // 6.4M float4
    if (i < nz4) ((float4*)g_z)[i] = make_float4(0.f, 0.f, 0.f, 0.f);
    if (i < R_TOT) ((float4*)g_den)[i] = make_float4(0.f, 0.f, 0.f, 0.f);
    if (i == 0) { g_wsum[0] = 0.0f; g_wsum[1] = 0.0f; }
}

// ---------------- per-node a1 = celu3(features @ attn1_w.T) -----------------
__global__ void __launch_bounds__(256) a1_kernel(
    const float* __restrict__ features, const float* __restrict__ attn1_w) {
    int warp = threadIdx.x >> 5, lane = threadIdx.x & 31;
    int node = blockIdx.x * 8 + warp;
    if (node >= N_NODES) return;
    float2 f = ((const float2*)features)[node * HC + lane];
    const float2* W1 = (const float2*)attn1_w;
    float r[4];
#pragma unroll
    for (int k = 0; k < 4; k++) {
        float2 w = W1[k * HC + lane];
        r[k] = w.x * f.x + w.y * f.y;
    }
#pragma unroll
    for (int off = 16; off; off >>= 1)
#pragma unroll
        for (int k = 0; k < 4; k++)
            r[k] += __shfl_xor_sync(0xffffffffu, r[k], off);
    if (lane == 0) {
#pragma unroll
        for (int k = 0; k < 4; k++) g_a1[node * 4 + k] = celu3f(r[k]);
    }
}

// ---------------- fused edge pass: gather+rotate+eft+logits+den+scatter -----
__global__ void __launch_bounds__(256) pass1_kernel(
    const float* __restrict__ features, const float* __restrict__ r_vec,
    const float* __restrict__ attn2, const int* __restrict__ inst_m, int m) {
    int warp = threadIdx.x >> 5, lane = threadIdx.x & 31;
    int e = blockIdx.x * 8 + warp;
    if (e >= E_EDGES) return;

    const float2* rv = (const float2*)r_vec;
    float2 ra = rv[(2 * m) * HC + lane];
    float2 rb = rv[(2 * m + 1) * HC + lane];
    float ia = rsqrtf(ra.x * ra.x + ra.y * ra.y);
    float ib = rsqrtf(rb.x * rb.x + rb.y * rb.y);
    ra.x *= ia; ra.y *= ia; rb.x *= ib; rb.y *= ib;
    float fr0x = rb.x * ra.x - rb.y * ra.y;
    float fr0y = rb.x * ra.y + rb.y * ra.x;

    const int* ip = inst_m + e * 3;
    int i0 = ip[0], i1 = ip[1], i2 = ip[2];
    const float2* F = (const float2*)features;
    float2 f0 = F[i0 * HC + lane];
    float2 f1 = F[i1 * HC + lane];
    float2 f2 = F[i2 * HC + lane];

    float mre = (f0.x * fr0x - f0.y * fr0y) + (f1.x * rb.x - f1.y * rb.y) + f2.x;
    float mim = (f0.x * fr0y + f0.y * fr0x) + (f1.x * rb.y + f1.y * rb.x) + f2.y;
    mre *= (1.0f / 3.0f); mim *= (1.0f / 3.0f);

    float se0 = celu3f(mre) * (1.0f / (1.0f + expf(-mre)));
    float se1 = celu3f(mim) * (1.0f / (1.0f + expf(-mim)));
    float ef0 = celu3f(se0), ef1 = celu3f(se1);

    // a2 = eft @ attn2.T (4 heads), full-butterfly so every lane has sums
    float r[4];
    const float2* W2 = (const float2*)attn2;
#pragma unroll
    for (int k = 0; k < 4; k++) {
        float2 w2 = W2[k * HC + lane];
        r[k] = w2.x * ef0 + w2.y * ef1;
    }
#pragma unroll
    for (int off = 16; off; off >>= 1)
#pragma unroll
        for (int k = 0; k < 4; k++)
            r[k] += __shfl_xor_sync(0xffffffffu, r[k], off);

    float4 a1v = *(const float4*)(g_a1 + (size_t)i0 * 4);
    float ex0 = expf(celu3f(a1v.x + r[0]));
    float ex1 = expf(celu3f(a1v.y + r[1]));
    float ex2 = expf(celu3f(a1v.z + r[2]));
    float ex3 = expf(celu3f(a1v.w + r[3]));

    size_t rowg = (size_t)m * N_NODES + i0;
    if (lane < 4) {
        float exv = lane == 0 ? ex0 : lane == 1 ? ex1 : lane == 2 ? ex2 : ex3;
        atomicAdd(g_den + rowg * 4 + lane, exv);
    }

    // pair-exchange so each lane holds 4 consecutive channels
    float p0 = __shfl_xor_sync(0xffffffffu, ef0, 1);
    float p1 = __shfl_xor_sync(0xffffffffu, ef1, 1);
    float v0, v1, v2, v3;
    if ((lane & 1) == 0) { v0 = ef0; v1 = ef1; v2 = p0; v3 = p1; }
    else                 { v0 = p0;  v1 = p1;  v2 = ef0; v3 = ef1; }
    int g4 = (lane >> 1) * 4;           // channel group base (0..60 step 4)
    int k0 = (lane & 1) * 2;            // heads {0,1} or {2,3}
    float exa = (lane & 1) ? ex2 : ex0;
    float exb = (lane & 1) ? ex3 : ex1;

    float* base = g_z + rowg * D;
    float* pa = base + k0 * H + g4;
    float* pb = base + (k0 + 1) * H + g4;
    asm volatile("red.global.add.v4.f32 [%0], {%1,%2,%3,%4};" ::
                 "l"(pa), "f"(exa * v0), "f"(exa * v1),
                 "f"(exa * v2), "f"(exa * v3) : "memory");
    asm volatile("red.global.add.v4.f32 [%0], {%1,%2,%3,%4};" ::
                 "l"(pb), "f"(exb * v0), "f"(exb * v1),
                 "f"(exb * v2), "f"(exb * v3) : "memory");
}

// ---------------- den -> reciprocal (guard isolated nodes) ------------------
__global__ void recip_kernel() {
    int i = blockIdx.x * blockDim.x + threadIdx.x;
    if (i < R_TOT * HEADS) {
        float d = g_den[i];
        g_den[i] = d > 0.0f ? 1.0f / d : 0.0f;
    }
}

// ---------------- MLP layer 1: t1 = celu3(fw1 @ celu3(z*inv) + fb1) ---------
// grid 148; per block: loop half (fw1 128-row panel in smem), loop row tiles.
__global__ void __launch_bounds__(256, 1) mlp_l1_kernel(
    const float* __restrict__ fw1, const float* __restrict__ fb1) {
    extern __shared__ float dsm[];
    float* Bs = dsm;                 // [128][ZST]
    float* zt = dsm + 128 * ZST;     // [TILE][ZST]
    int tid = threadIdx.x;
    int w = tid >> 5, lane = tid & 31;
    int rg = w & 1, cq = w >> 1;     // row-group (16), col-quarter (32)

    for (int half = 0; half < 2; half++) {
        __syncthreads();
        // stage fw1 half -> smem (tf32-rounded)
        for (int i = tid; i < 128 * 256; i += 256) {
            int n = i >> 8, k = i & 255;
            Bs[n * ZST + k] =
                __uint_as_float(tf32r(fw1[(size_t)(half * 128 + n) * 256 + k]));
        }
        __syncthreads();

        for (int t = blockIdx.x; t < NTILES; t += GRID_MLP) {
            // stage z tile: celu3(z * inv_den), tf32-rounded
            int head = tid >> 6;
#pragma unroll 4
            for (int r = 0; r < TILE; r++) {
                int row = t * TILE + r;
                float inv = g_den[(size_t)row * 4 + head];
                float z = g_z[(size_t)row * D + tid];
                zt[r * ZST + tid] = __uint_as_float(tf32r(celu3f(z * inv)));
            }
            __syncthreads();

            float acc[4][4];
#pragma unroll
            for (int nb = 0; nb < 4; nb++)
#pragma unroll
                for (int c = 0; c < 4; c++) acc[nb][c] = 0.0f;

            int arow = (rg * 16 + (lane >> 2)) * ZST + (lane & 3);
#pragma unroll 4
            for (int ks = 0; ks < 32; ks++) {
                int k0 = ks * 8;
                unsigned a[4];
                a[0] = __float_as_uint(zt[arow + k0]);
                a[1] = __float_as_uint(zt[arow + 8 * ZST + k0]);
                a[2] = __float_as_uint(zt[arow + k0 + 4]);
                a[3] = __float_as_uint(zt[arow + 8 * ZST + k0 + 4]);
#pragma unroll
                for (int nb = 0; nb < 4; nb++) {
                    int bn = (cq * 32 + nb * 8 + (lane >> 2)) * ZST + k0 + (lane & 3);
                    unsigned b[2];
                    b[0] = __float_as_uint(Bs[bn]);
                    b[1] = __float_as_uint(Bs[bn + 4]);
                    mma_tf32(acc[nb], a, b);
                }
            }
            __syncthreads();

            // bias + celu -> zt (local cols 0..127), then coalesced copy-out
            int rowl = rg * 16 + (lane >> 2);
#pragma unroll
            for (int nb = 0; nb < 4; nb++) {
                int n = cq * 32 + nb * 8 + 2 * (lane & 3);
                float b0f = fb1[half * 128 + n];
                float b1f = fb1[half * 128 + n + 1];
                zt[rowl * ZST + n]           = celu3f(acc[nb][0] + b0f);
                zt[rowl * ZST + n + 1]       = celu3f(acc[nb][1] + b1f);
                zt[(rowl + 8) * ZST + n]     = celu3f(acc[nb][2] + b0f);
                zt[(rowl + 8) * ZST + n + 1] = celu3f(acc[nb][3] + b1f);
            }
            __syncthreads();

            int r = tid >> 3, cb = (tid & 7) * 16;
            size_t gb = (size_t)(t * TILE + r) * D + half * 128 + cb;
#pragma unroll
            for (int i = 0; i < 4; i++) {
                float4 v = *(const float4*)&zt[r * ZST + cb + 4 * i];
                *(float4*)(g_t1 + gb + 4 * i) = v;
            }
            __syncthreads();
        }
    }
}

// ---------------- MLP layer 2 + 3: w-sums -----------------------------------
__global__ void __launch_bounds__(256, 1) mlp_l2_kernel(
    const float* __restrict__ fw2, const float* __restrict__ fb2,
    const float* __restrict__ fw3) {
    extern __shared__ float dsm[];
    float* Bs = dsm;                 // [128][ZST]
    float* zt = dsm + 128 * ZST;     // [TILE][ZST]
    int tid = threadIdx.x;
    int w = tid >> 5, lane = tid & 31;
    int rg = w & 1, cq = w >> 1;

    // stage fw2 (tf32-rounded)
    for (int i = tid; i < 128 * 256; i += 256) {
        int n = i >> 8, k = i & 255;
        Bs[n * ZST + k] = __uint_as_float(tf32r(fw2[(size_t)n * 256 + k]));
    }
    // per-lane bias / fw3 for its 8 output cols
    float fb2c[8], fw3c[8];
#pragma unroll
    for (int nb = 0; nb < 4; nb++) {
        int n = cq * 32 + nb * 8 + 2 * (lane & 3);
        fb2c[2 * nb] = fb2[n];     fb2c[2 * nb + 1] = fb2[n + 1];
        fw3c[2 * nb] = fw3[n];     fw3c[2 * nb + 1] = fw3[n + 1];
    }
    __syncthreads();

    float vsum0 = 0.0f, vsum1 = 0.0f;

    for (int t = blockIdx.x; t < NTILES; t += GRID_MLP) {
#pragma unroll 4
        for (int r = 0; r < TILE; r++) {
            float v = g_t1[(size_t)(t * TILE + r) * D + tid];
            zt[r * ZST + tid] = __uint_as_float(tf32r(v));
        }
        __syncthreads();

        float acc[4][4];
#pragma unroll
        for (int nb = 0; nb < 4; nb++)
#pragma unroll
            for (int c = 0; c < 4; c++) acc[nb][c] = 0.0f;

        int arow = (rg * 16 + (lane >> 2)) * ZST + (lane & 3);
#pragma unroll 4
        for (int ks = 0; ks < 32; ks++) {
            int k0 = ks * 8;
            unsigned a[4];
            a[0] = __float_as_uint(zt[arow + k0]);
            a[1] = __float_as_uint(zt[arow + 8 * ZST + k0]);
            a[2] = __float_as_uint(zt[arow + k0 + 4]);
            a[3] = __float_as_uint(zt[arow + 8 * ZST + k0 + 4]);
#pragma unroll
            for (int nb = 0; nb < 4; nb++) {
                int bn = (cq * 32 + nb * 8 + (lane >> 2)) * ZST + k0 + (lane & 3);
                unsigned b[2];
                b[0] = __float_as_uint(Bs[bn]);
                b[1] = __float_as_uint(Bs[bn + 4]);
                mma_tf32(acc[nb], a, b);
            }
        }

        int row_lo = t * TILE + rg * 16 + (lane >> 2);
        int row_hi = row_lo + 8;
        float clo = 0.0f, chi = 0.0f;
#pragma unroll
        for (int nb = 0; nb < 4; nb++) {
            clo += fw3c[2 * nb]     * celu3f(acc[nb][0] + fb2c[2 * nb]);
            clo += fw3c[2 * nb + 1] * celu3f(acc[nb][1] + fb2c[2 * nb + 1]);
            chi += fw3c[2 * nb]     * celu3f(acc[nb][2] + fb2c[2 * nb]);
            chi += fw3c[2 * nb + 1] * celu3f(acc[nb][3] + fb2c[2 * nb + 1]);
        }
        if (row_lo < N_NODES) vsum0 += clo; else vsum1 += clo;
        if (row_hi < N_NODES) vsum0 += chi; else vsum1 += chi;
        __syncthreads();
    }

#pragma unroll
    for (int off = 16; off; off >>= 1) {
        vsum0 += __shfl_xor_sync(0xffffffffu, vsum0, off);
        vsum1 += __shfl_xor_sync(0xffffffffu, vsum1, off);
    }
    if (lane == 0) {
        atomicAdd(&g_wsum[0], vsum0);
        atomicAdd(&g_wsum[1], vsum1);
    }
}

__global__ void beta_kernel() {
    float w0 = g_wsum[0] * (1.0f / (float)N_NODES);
    float w1 = g_wsum[1] * (1.0f / (float)N_NODES);
    float mx = fmaxf(w0, w1);
    float e0 = expf(w0 - mx), e1 = expf(w1 - mx);
    float inv = 1.0f / (e0 + e1);
    g_beta[0] = e0 * inv;
    g_beta[1] = e1 * inv;
}

__global__ void combine_kernel(float* __restrict__ out) {
    int i = blockIdx.x * blockDim.x + threadIdx.x;
    int n4 = N_NODES * D / 4;
    if (i < n4) {
        int f = i * 4;
        int node = f >> 8;
        int head = (f & 255) >> 6;
        float inv0 = g_den[(size_t)node * 4 + head];
        float inv1 = g_den[(size_t)(N_NODES + node) * 4 + head];
        float b0 = g_beta[0], b1 = g_beta[1];
        float4 a = ((const float4*)g_z)[i];
        float4 c = ((const float4*)(g_z + (size_t)N_NODES * D))[i];
        float4 o;
        o.x = b0 * celu3f(a.x * inv0) + b1 * celu3f(c.x * inv1);
        o.y = b0 * celu3f(a.y * inv0) + b1 * celu3f(c.y * inv1);
        o.z = b0 * celu3f(a.z * inv0) + b1 * celu3f(c.z * inv1);
        o.w = b0 * celu3f(a.w * inv0) + b1 * celu3f(c.w * inv1);
        ((float4*)out)[i] = o;
    }
}

extern "C" void kernel_launch(void* const* d_in, const int* in_sizes, int n_in,
                              void* d_out, int out_size) {
    const float* features = (const float*)d_in[0];
    const float* r_vec    = (const float*)d_in[1];
    const float* attn1_w  = (const float*)d_in[2];
    const float* attn2    = (const float*)d_in[3];
    const float* fw1      = (const float*)d_in[4];
    const float* fb1      = (const float*)d_in[5];
    const float* fw2      = (const float*)d_in[6];
    const float* fb2      = (const float*)d_in[7];
    const float* fw3      = (const float*)d_in[8];
    const int*   inst     = (const int*)d_in[9];
    float* out = (float*)d_out;

    cudaFuncSetAttribute(mlp_l1_kernel,
                         cudaFuncAttributeMaxDynamicSharedMemorySize, SMEM_MLP);
    cudaFuncSetAttribute(mlp_l2_kernel,
                         cudaFuncAttributeMaxDynamicSharedMemorySize, SMEM_MLP);

    zero_all_kernel<<<(R_TOT * D / 4 + 255) / 256, 256>>>();            // 1
    a1_kernel<<<(N_NODES + 7) / 8, 256>>>(features, attn1_w);           // 2
    for (int m = 0; m < M_PATHS; m++) {                                 // 3,4
        const int* inst_m = inst + (size_t)m * E_EDGES * P_LEN;
        pass1_kernel<<<E_EDGES / 8, 256>>>(features, r_vec, attn2, inst_m, m);
    }
    recip_kernel<<<(R_TOT * HEADS + 255) / 256, 256>>>();               // 5
    mlp_l1_kernel<<<GRID_MLP, 256, SMEM_MLP>>>(fw1, fb1);               // 6 (ncu)
    mlp_l2_kernel<<<GRID_MLP, 256, SMEM_MLP>>>(fw2, fb2, fw3);          // 7
    beta_kernel<<<1, 1>>>();                                            // 8
    combine_kernel<<<(N_NODES * D / 4 + 255) / 256, 256>>>(out);        // 9
}

// round 8
// speedup vs baseline: 2.2018x; 2.2018x over previous
#include <cuda_runtime.h>
#include <cuda_bf16.h>

#define N_NODES 50000
#define HC 32
#define H 64
#define M_PATHS 2
#define E_EDGES 250000
#define P_LEN 3
#define D 256
#define R_TOT (M_PATHS * N_NODES)
#define MLP_TILES 782              // ceil(100000/128)
#define GRID_MLP 148
#define THREADS_MLP 512
#define SMEM_FUSED 131072          // As 64KB + T1s 64KB

__device__ float g_den[R_TOT * 4];
__device__ float g_a1[N_NODES * 4];
__device__ float g_z[(size_t)R_TOT * D];
__device__ float g_wsum[2];
__device__ float g_beta[2];

__device__ __forceinline__ float celu3f(float x) {
    return x > 0.0f ? x : 3.0f * expm1f(x * (1.0f / 3.0f));
}
__device__ __forceinline__ unsigned smem_u32(const void* p) {
    unsigned a;
    asm("{ .reg .u64 t; cvta.to.shared.u64 t, %1; cvt.u32.u64 %0, t; }"
        : "=r"(a) : "l"(p));
    return a;
}
__device__ __forceinline__ unsigned bfpack(float a, float b) {
    __nv_bfloat162 p = __floats2bfloat162_rn(a, b);
    return *reinterpret_cast<unsigned*>(&p);
}
__device__ __forceinline__ void ldmatrix_x4(unsigned* r, unsigned addr) {
    asm volatile("ldmatrix.sync.aligned.m8n8.x4.shared.b16 {%0,%1,%2,%3}, [%4];"
                 : "=r"(r[0]), "=r"(r[1]), "=r"(r[2]), "=r"(r[3]) : "r"(addr));
}
__device__ __forceinline__ void mma_bf16(float* c, const unsigned* a,
                                         const unsigned* b) {
    asm volatile(
        "mma.sync.aligned.m16n8k16.row.col.f32.bf16.bf16.f32 "
        "{%0,%1,%2,%3}, {%4,%5,%6,%7}, {%8,%9}, {%0,%1,%2,%3};"
        : "+f"(c[0]), "+f"(c[1]), "+f"(c[2]), "+f"(c[3])
        : "r"(a[0]), "r"(a[1]), "r"(a[2]), "r"(a[3]), "r"(b[0]), "r"(b[1]));
}

__global__ void zero_all_kernel() {
    int i = blockIdx.x * blockDim.x + threadIdx.x;
    if (i < R_TOT * D / 4) ((float4*)g_z)[i] = make_float4(0.f, 0.f, 0.f, 0.f);
    if (i < R_TOT) ((float4*)g_den)[i] = make_float4(0.f, 0.f, 0.f, 0.f);
    if (i == 0) { g_wsum[0] = 0.0f; g_wsum[1] = 0.0f; }
}

__global__ void __launch_bounds__(256) a1_kernel(
    const float* __restrict__ features, const float* __restrict__ attn1_w) {
    int warp = threadIdx.x >> 5, lane = threadIdx.x & 31;
    int node = blockIdx.x * 8 + warp;
    if (node >= N_NODES) return;
    float2 f = ((const float2*)features)[node * HC + lane];
    const float2* W1 = (const float2*)attn1_w;
    float r[4];
#pragma unroll
    for (int k = 0; k < 4; k++) {
        float2 w = W1[k * HC + lane];
        r[k] = w.x * f.x + w.y * f.y;
    }
#pragma unroll
    for (int off = 16; off; off >>= 1)
#pragma unroll
        for (int k = 0; k < 4; k++)
            r[k] += __shfl_xor_sync(0xffffffffu, r[k], off);
    if (lane == 0)
#pragma unroll
        for (int k = 0; k < 4; k++) g_a1[node * 4 + k] = celu3f(r[k]);
}

__global__ void __launch_bounds__(256) pass1_kernel(
    const float* __restrict__ features, const float* __restrict__ r_vec,
    const float* __restrict__ attn2, const int* __restrict__ inst) {
    int warp = threadIdx.x >> 5, lane = threadIdx.x & 31;
    int e = blockIdx.x * 8 + warp;
    int m = blockIdx.y;
    if (e >= E_EDGES) return;
    const int* ip = inst + (size_t)m * E_EDGES * P_LEN + e * 3;

    const float2* rv = (const float2*)r_vec;
    float2 ra = rv[(2 * m) * HC + lane];
    float2 rb = rv[(2 * m + 1) * HC + lane];
    float ia = rsqrtf(ra.x * ra.x + ra.y * ra.y);
    float ib = rsqrtf(rb.x * rb.x + rb.y * rb.y);
    ra.x *= ia; ra.y *= ia; rb.x *= ib; rb.y *= ib;
    float fr0x = rb.x * ra.x - rb.y * ra.y;
    float fr0y = rb.x * ra.y + rb.y * ra.x;

    int i0 = ip[0], i1 = ip[1], i2 = ip[2];
    const float2* F = (const float2*)features;
    float2 f0 = F[i0 * HC + lane];
    float2 f1 = F[i1 * HC + lane];
    float2 f2 = F[i2 * HC + lane];

    float mre = (f0.x * fr0x - f0.y * fr0y) + (f1.x * rb.x - f1.y * rb.y) + f2.x;
    float mim = (f0.x * fr0y + f0.y * fr0x) + (f1.x * rb.y + f1.y * rb.x) + f2.y;
    mre *= (1.0f / 3.0f); mim *= (1.0f / 3.0f);

    float se0 = celu3f(mre) * (1.0f / (1.0f + expf(-mre)));
    float se1 = celu3f(mim) * (1.0f / (1.0f + expf(-mim)));
    float ef0 = celu3f(se0), ef1 = celu3f(se1);

    // a2 partials; folded reduction -> lane ends with sum for head (lane&3)
    const float2* W2 = (const float2*)attn2;
    float2 w0 = W2[0 * HC + lane], w1 = W2[1 * HC + lane];
    float2 w2 = W2[2 * HC + lane], w3 = W2[3 * HC + lane];
    float r0 = w0.x * ef0 + w0.y * ef1;
    float r1 = w1.x * ef0 + w1.y * ef1;
    float r2 = w2.x * ef0 + w2.y * ef1;
    float r3 = w3.x * ef0 + w3.y * ef1;
    float tA = __shfl_xor_sync(0xffffffffu, (lane & 1) ? r0 : r1, 1);
    float s01 = ((lane & 1) ? r1 : r0) + tA;
    float tB = __shfl_xor_sync(0xffffffffu, (lane & 1) ? r2 : r3, 1);
    float s23 = ((lane & 1) ? r3 : r2) + tB;
    float tC = __shfl_xor_sync(0xffffffffu, (lane & 2) ? s01 : s23, 2);
    float v = ((lane & 2) ? s23 : s01) + tC;
    v += __shfl_xor_sync(0xffffffffu, v, 4);
    v += __shfl_xor_sync(0xffffffffu, v, 8);
    v += __shfl_xor_sync(0xffffffffu, v, 16);

    float4 a1v = *(const float4*)(g_a1 + (size_t)i0 * 4);
    int hk = lane & 3;
    float a1h = hk == 0 ? a1v.x : hk == 1 ? a1v.y : hk == 2 ? a1v.z : a1v.w;
    float exval = expf(celu3f(a1h + v));   // logits bounded; no max-sub needed

    size_t rowg = (size_t)m * N_NODES + i0;
    if (lane < 4) atomicAdd(g_den + rowg * 4 + lane, exval);

    int k0 = (lane & 1) * 2;
    int base4 = lane & 28;
    float exa = __shfl_sync(0xffffffffu, exval, base4 | k0);
    float exb = __shfl_sync(0xffffffffu, exval, base4 | (k0 + 1));

    float p0 = __shfl_xor_sync(0xffffffffu, ef0, 1);
    float p1 = __shfl_xor_sync(0xffffffffu, ef1, 1);
    float v0, v1, v2, v3;
    if ((lane & 1) == 0) { v0 = ef0; v1 = ef1; v2 = p0; v3 = p1; }
    else                 { v0 = p0;  v1 = p1;  v2 = ef0; v3 = ef1; }
    int g4 = (lane >> 1) * 4;

    float* base = g_z + rowg * D;
    float* pa = base + k0 * H + g4;
    float* pb = base + (k0 + 1) * H + g4;
    asm volatile("red.global.add.v4.f32 [%0], {%1,%2,%3,%4};" ::
                 "l"(pa), "f"(exa * v0), "f"(exa * v1),
                 "f"(exa * v2), "f"(exa * v3) : "memory");
    asm volatile("red.global.add.v4.f32 [%0], {%1,%2,%3,%4};" ::
                 "l"(pb), "f"(exb * v0), "f"(exb * v1),
                 "f"(exb * v2), "f"(exb * v3) : "memory");
}

__global__ void recip_kernel() {
    int i = blockIdx.x * blockDim.x + threadIdx.x;
    if (i < R_TOT * 4) {
        float d = g_den[i];
        g_den[i] = d > 0.0f ? 1.0f / d : 0.0f;
    }
}

// ---- Fused MLP: L1+L2+L3 with bf16 mma.sync, weights as register frags -----
// 16 warps. L1: warp w -> cols [w*16, w*16+16). L2: warp w -> cols [w*8, +8).
// A/t1 tiles in smem, XOR-chunk swizzle: chunk' = chunk ^ (row & 7).
__global__ void __launch_bounds__(THREADS_MLP, 1) mlp_fused(
    const float* __restrict__ fw1, const float* __restrict__ fb1,
    const float* __restrict__ fw2, const float* __restrict__ fb2,
    const float* __restrict__ fw3) {
    extern __shared__ char smem[];
    const unsigned sbA = smem_u32(smem);
    const unsigned sbT = sbA + 65536;
    int tid = threadIdx.x, w = tid >> 5, l = tid & 31;
    int lq = l >> 2, lr = l & 3;

    // B1 fragments: fw1 cols w*16..+15, all K=256
    unsigned B1[2][16][2];
#pragma unroll
    for (int nt = 0; nt < 2; nt++) {
        int col = w * 16 + nt * 8 + lq;
#pragma unroll
        for (int kt = 0; kt < 16; kt++) {
            const float* p = fw1 + (size_t)col * 256 + kt * 16 + lr * 2;
            B1[nt][kt][0] = bfpack(p[0], p[1]);
            B1[nt][kt][1] = bfpack(p[8], p[9]);
        }
    }
    // B2 fragments: fw2 col w*8 + lq
    unsigned B2[16][2];
    {
        int col = w * 8 + lq;
#pragma unroll
        for (int kt = 0; kt < 16; kt++) {
            const float* p = fw2 + (size_t)col * 256 + kt * 16 + lr * 2;
            B2[kt][0] = bfpack(p[0], p[1]);
            B2[kt][1] = bfpack(p[8], p[9]);
        }
    }
    float fb1c[2][2], fb2c[2], fw3c[2];
#pragma unroll
    for (int nt = 0; nt < 2; nt++) {
        fb1c[nt][0] = fb1[w * 16 + nt * 8 + lr * 2];
        fb1c[nt][1] = fb1[w * 16 + nt * 8 + lr * 2 + 1];
    }
    fb2c[0] = fb2[w * 8 + lr * 2];     fb2c[1] = fb2[w * 8 + lr * 2 + 1];
    fw3c[0] = fw3[w * 8 + lr * 2];     fw3c[1] = fw3[w * 8 + lr * 2 + 1];

    float vs0 = 0.0f, vs1 = 0.0f;

    for (int t = blockIdx.x; t < MLP_TILES; t += GRID_MLP) {
        int r0 = t * 128;
        // ---- stage A = celu3(z * inv_den) as bf16, swizzled ----
#pragma unroll
        for (int i = tid; i < 4096; i += THREADS_MLP) {
            int r = i >> 5, c = i & 31;
            int gr = r0 + r;
            unsigned off = r * 512 + ((unsigned)(c ^ (r & 7)) << 4);
            uint4 pk = make_uint4(0u, 0u, 0u, 0u);
            if (gr < R_TOT) {
                float inv = g_den[(size_t)gr * 4 + (c >> 3)];
                const float4* zp = (const float4*)(g_z + (size_t)gr * 256 + c * 8);
                float4 za = zp[0], zb = zp[1];
                pk = make_uint4(
                    bfpack(celu3f(za.x * inv), celu3f(za.y * inv)),
                    bfpack(celu3f(za.z * inv), celu3f(za.w * inv)),
                    bfpack(celu3f(zb.x * inv), celu3f(zb.y * inv)),
                    bfpack(celu3f(zb.z * inv), celu3f(zb.w * inv)));
            }
            *(uint4*)(smem + off) = pk;
        }
        __syncthreads();   // also protects T1s: prior-iter L2 reads done

        // ---- layer 1: t1 = celu3(A @ fw1.T + fb1) -> smem T1s --------------
#pragma unroll 2
        for (int mt = 0; mt < 8; mt++) {
            int m0 = mt * 16;
            float acc[2][4] = {{0.f, 0.f, 0.f, 0.f}, {0.f, 0.f, 0.f, 0.f}};
            int arow = m0 + (l & 15);
#pragma unroll
            for (int kt = 0; kt < 16; kt++) {
                unsigned a[4];
                unsigned ad = sbA + arow * 512 +
                              ((unsigned)((2 * kt + (l >> 4)) ^ (arow & 7)) << 4);
                ldmatrix_x4(a, ad);
                mma_bf16(acc[0], a, B1[0][kt]);
                mma_bf16(acc[1], a, B1[1][kt]);
            }
            int rlo = m0 + lq, rhi = rlo + 8;
#pragma unroll
            for (int nt = 0; nt < 2; nt++) {
                int col = w * 16 + nt * 8 + lr * 2;
                unsigned clo = bfpack(celu3f(acc[nt][0] + fb1c[nt][0]),
                                      celu3f(acc[nt][1] + fb1c[nt][1]));
                unsigned chi = bfpack(celu3f(acc[nt][2] + fb1c[nt][0]),
                                      celu3f(acc[nt][3] + fb1c[nt][1]));
                unsigned olo = 65536 + rlo * 512 +
                               ((unsigned)((col >> 3) ^ (rlo & 7)) << 4) + (col & 7) * 2;
                unsigned ohi = 65536 + rhi * 512 +
                               ((unsigned)((col >> 3) ^ (rhi & 7)) << 4) + (col & 7) * 2;
                *(unsigned*)(smem + olo) = clo;
                *(unsigned*)(smem + ohi) = chi;
            }
        }
        __syncthreads();

        // ---- layer 2+3: per-row scalar = fw3 . celu3(t1 @ fw2.T + fb2) -----
#pragma unroll 2
        for (int mt = 0; mt < 8; mt++) {
            int m0 = mt * 16;
            float acc[4] = {0.f, 0.f, 0.f, 0.f};
            int arow = m0 + (l & 15);
#pragma unroll
            for (int kt = 0; kt < 16; kt++) {
                unsigned a[4];
                unsigned ad = sbT + arow * 512 +
                              ((unsigned)((2 * kt + (l >> 4)) ^ (arow & 7)) << 4);
                ldmatrix_x4(a, ad);
                mma_bf16(acc, a, B2[kt]);
            }
            int rlo = r0 + m0 + lq, rhi = rlo + 8;
            float slo = celu3f(acc[0] + fb2c[0]) * fw3c[0] +
                        celu3f(acc[1] + fb2c[1]) * fw3c[1];
            float shi = celu3f(acc[2] + fb2c[0]) * fw3c[0] +
                        celu3f(acc[3] + fb2c[1]) * fw3c[1];
            if (rlo < N_NODES) vs0 += slo; else if (rlo < R_TOT) vs1 += slo;
            if (rhi < N_NODES) vs0 += shi; else if (rhi < R_TOT) vs1 += shi;
        }
        // no sync: next staging writes As only; sync-after-stage covers T1s
    }

    // ---- block reduction of vs0/vs1 ----
#pragma unroll
    for (int off = 16; off; off >>= 1) {
        vs0 += __shfl_xor_sync(0xffffffffu, vs0, off);
        vs1 += __shfl_xor_sync(0xffffffffu, vs1, off);
    }
    __syncthreads();
    float* red = (float*)smem;
    if (l == 0) { red[w] = vs0; red[16 + w] = vs1; }
    __syncthreads();
    if (tid == 0) {
        float a0 = 0.f, a1 = 0.f;
#pragma unroll
        for (int i = 0; i < 16; i++) { a0 += red[i]; a1 += red[16 + i]; }
        atomicAdd(&g_wsum[0], a0);
        atomicAdd(&g_wsum[1], a1);
    }
}

__global__ void beta_kernel() {
    float w0 = g_wsum[0] * (1.0f / (float)N_NODES);
    float w1 = g_wsum[1] * (1.0f / (float)N_NODES);
    float mx = fmaxf(w0, w1);
    float e0 = expf(w0 - mx), e1 = expf(w1 - mx);
    float inv = 1.0f / (e0 + e1);
    g_beta[0] = e0 * inv;
    g_beta[1] = e1 * inv;
}

__global__ void combine_kernel(float* __restrict__ out) {
    int i = blockIdx.x * blockDim.x + threadIdx.x;
    if (i < N_NODES * D / 4) {
        int f = i * 4;
        int node = f >> 8;
        int head = (f & 255) >> 6;
        float inv0 = g_den[(size_t)node * 4 + head];
        float inv1 = g_den[(size_t)(N_NODES + node) * 4 + head];
        float b0 = g_beta[0], b1 = g_beta[1];
        float4 a = ((const float4*)g_z)[i];
        float4 c = ((const float4*)(g_z + (size_t)N_NODES * D))[i];
        float4 o;
        o.x = b0 * celu3f(a.x * inv0) + b1 * celu3f(c.x * inv1);
        o.y = b0 * celu3f(a.y * inv0) + b1 * celu3f(c.y * inv1);
        o.z = b0 * celu3f(a.z * inv0) + b1 * celu3f(c.z * inv1);
        o.w = b0 * celu3f(a.w * inv0) + b1 * celu3f(c.w * inv1);
        ((float4*)out)[i] = o;
    }
}

extern "C" void kernel_launch(void* const* d_in, const int* in_sizes, int n_in,
                              void* d_out, int out_size) {
    const float* features = (const float*)d_in[0];
    const float* r_vec    = (const float*)d_in[1];
    const float* attn1_w  = (const float*)d_in[2];
    const float* attn2    = (const float*)d_in[3];
    const float* fw1      = (const float*)d_in[4];
    const float* fb1      = (const float*)d_in[5];
    const float* fw2      = (const float*)d_in[6];
    const float* fb2      = (const float*)d_in[7];
    const float* fw3      = (const float*)d_in[8];
    const int*   inst     = (const int*)d_in[9];
    float* out = (float*)d_out;

    cudaFuncSetAttribute(mlp_fused,
                         cudaFuncAttributeMaxDynamicSharedMemorySize, SMEM_FUSED);

    zero_all_kernel<<<(R_TOT * D / 4 + 255) / 256, 256>>>();
    a1_kernel<<<(N_NODES + 7) / 8, 256>>>(features, attn1_w);
    pass1_kernel<<<dim3(E_EDGES / 8, 2), 256>>>(features, r_vec, attn2, inst);
    recip_kernel<<<(R_TOT * 4 + 255) / 256, 256>>>();
    mlp_fused<<<GRID_MLP, THREADS_MLP, SMEM_FUSED>>>(fw1, fb1, fw2, fb2, fw3);
    beta_kernel<<<1, 1>>>();
    combine_kernel<<<(N_NODES * D / 4 + 255) / 256, 256>>>(out);
}